// round 6
// baseline (speedup 1.0000x reference)
#include <cuda_runtime.h>
#include <cuda_bf16.h>

#define NMAX 100000
#define DH   64
#define GMAX 64
#define DOUT 32
#define BMAX 65   // <= 64 thresholds -> <= 65 buckets

// ---- scratch ---------------------------------------------------------------
__device__ __align__(256) float2 d_pq[(size_t)BMAX * NMAX];  // (p,q), [b][i]
__device__ __align__(256) float4 d_ninfo[NMAX];              // (a=dinv*c, dinv, bits(b), 0)
__device__ float d_S[NMAX];          // S, then reused as c
__device__ float d_dinv[NMAX];
__device__ int   d_deg[NMAX];
__device__ float d_u[BMAX * DH];
__device__ float d_w[BMAX * DH];
__device__ float d_tsort[DH];
__device__ float d_v[DH];
__device__ float d_b1s[DH];
__device__ int   d_Beff;
__device__ unsigned d_cminb, d_cmaxb;
__device__ int   d_gstart[GMAX + 2];
__device__ float d_pooled[GMAX * DH];
__device__ unsigned d_barcnt = 0;
__device__ unsigned d_bardone = 0;

// monotonic-counter grid barrier; counters reset at kernel exit
__device__ __forceinline__ void grid_barrier(unsigned phase) {
    __syncthreads();
    if (threadIdx.x == 0) {
        __threadfence();
        atomicAdd(&d_barcnt, 1u);
        unsigned target = gridDim.x * phase;
        unsigned v;
        for (;;) {
            asm volatile("ld.acquire.gpu.u32 %0, [%1];" : "=r"(v) : "l"(&d_barcnt));
            if (v >= target) break;
            __nanosleep(128);
        }
    }
    __syncthreads();
}

__global__ __launch_bounds__(256, 2)
void k_all(const int* __restrict__ ei, const int* __restrict__ batch,
           const float* __restrict__ emb, const float* __restrict__ W1,
           const float* __restrict__ b1, const float* __restrict__ W2,
           const float* __restrict__ b2, const float* __restrict__ fcW,
           const float* __restrict__ fcb, float* __restrict__ out,
           int N, int E, int G) {
    __shared__ float su[BMAX * DH];
    __shared__ float sw[BMAX * DH];
    __shared__ float swarp[8][DH];
    __shared__ float sb2[DH];
    __shared__ float st[DH];
    __shared__ int   sinr[DH];
    __shared__ float sh[DH], sbv[DH];
    __shared__ int   sg0;

    const unsigned tid  = threadIdx.x;
    const unsigned gtid = blockIdx.x * blockDim.x + tid;
    const unsigned gsz  = gridDim.x * blockDim.x;

    // ---- P0: zero scratch ----
    for (int i = gtid; i < N; i += gsz) { d_deg[i] = 0; d_S[i] = 0.f; }
    for (int i = gtid; i < GMAX * DH; i += gsz) d_pooled[i] = 0.f;
    if (gtid == 0) { d_cminb = 0x7f800000u; d_cmaxb = 0u; }
    grid_barrier(1);

    // ---- P1: in-degree on dst ----
    for (int e = gtid; e < E; e += gsz) atomicAdd(&d_deg[ei[E + e]], 1);
    grid_barrier(2);

    // ---- P2: S[dst] += rsqrt(deg[src]+1) ----
    for (int e = gtid; e < E; e += gsz)
        atomicAdd(&d_S[ei[E + e]], rsqrtf((float)d_deg[ei[e]] + 1.0f));
    grid_barrier(3);

    // ---- P3: dinv, c = dinv*(S+dinv), global min/max of c ----
    {
        unsigned mn = 0x7f800000u, mx = 0u;
        for (int i = gtid; i < N; i += gsz) {
            float dv = rsqrtf((float)d_deg[i] + 1.0f);
            float c  = dv * (d_S[i] + dv);
            d_dinv[i] = dv; d_S[i] = c;
            unsigned cb = __float_as_uint(c);      // c>0: bit order == float order
            mn = min(mn, cb); mx = max(mx, cb);
        }
        mn = __reduce_min_sync(0xffffffffu, mn);
        mx = __reduce_max_sync(0xffffffffu, mx);
        if ((tid & 31) == 0) { atomicMin(&d_cminb, mn); atomicMax(&d_cmaxb, mx); }
    }
    grid_barrier(4);

    // ---- P4: block 0: v = emb@W1, in-range thresholds, rank sort ----
    if (blockIdx.x == 0) {
        if (tid < DH) {
            float a = 0.f;
            #pragma unroll
            for (int k = 0; k < DH; k++) a = fmaf(emb[k], W1[k * DH + tid], a);
            float bb = b1[tid];
            d_v[tid] = a; d_b1s[tid] = bb;
            float cmin = __uint_as_float(d_cminb);
            float cmax = __uint_as_float(d_cmaxb);
            float th = -bb / a;                    // NaN/inf auto-fail range test
            int inr = (a != 0.f) && (th > cmin) && (th < cmax);
            st[tid] = th; sinr[tid] = inr;
        }
        __syncthreads();
        if (tid < DH && sinr[tid]) {
            float th = st[tid]; int r = 0;
            for (int d = 0; d < DH; d++)
                if (sinr[d] && (st[d] < th || (st[d] == th && (int)d < (int)tid))) r++;
            d_tsort[r] = th;
        }
        if (tid == 0) {
            int cc = 0;
            for (int d = 0; d < DH; d++) cc += sinr[d];
            d_Beff = cc + 1;
        }
    }
    grid_barrier(5);

    // ---- P5: uw tables (blocks < BMAX) || bucket/ninfo/pq-zero/gstart (rest) ----
    {
        int Beff = d_Beff;
        float cmin = __uint_as_float(d_cminb);
        float cmax = __uint_as_float(d_cmaxb);
        if (blockIdx.x < BMAX) {
            int b = blockIdx.x;
            if (b < Beff) {
                float lo = (b == 0)        ? cmin : d_tsort[b - 1];
                float hi = (b == Beff - 1) ? cmax : d_tsort[b];
                float rep = 0.5f * (lo + hi);
                if (tid < DH) {
                    float vv = d_v[tid], bb = d_b1s[tid];
                    int act = fmaf(rep, vv, bb) > 0.f;
                    sh[tid]  = act ? vv : 0.f;
                    sbv[tid] = act ? bb : 0.f;
                }
                __syncthreads();
                if (tid < DH) {
                    float uu = 0.f, ww = 0.f;
                    #pragma unroll 8
                    for (int d = 0; d < DH; d++) {
                        float wdj = W2[d * DH + tid];   // coalesced across tid
                        uu = fmaf(sh[d],  wdj, uu);
                        ww = fmaf(sbv[d], wdj, ww);
                    }
                    d_u[b * DH + tid] = uu;
                    d_w[b * DH + tid] = ww;
                }
            }
        } else {
            int base   = (blockIdx.x - BMAX) * blockDim.x + tid;
            int stride = (gridDim.x - BMAX) * blockDim.x;
            int cnt = Beff - 1;
            for (int i = base; i <= N; i += stride) {
                if (i < N) {
                    float c  = d_S[i];
                    float dv = d_dinv[i];
                    int bb = 0;
                    for (int k = 0; k < cnt; k++) bb += (d_tsort[k] < c);
                    d_ninfo[i] = make_float4(dv * c, dv, __int_as_float(bb), 0.f);
                    float2 z = make_float2(0.f, 0.f);
                    for (int b2 = 0; b2 < Beff; b2++)
                        d_pq[(size_t)b2 * N + i] = z;
                }
                int cur  = (i < N) ? batch[i] : G;
                int prev = (i == 0) ? -1 : batch[i - 1];
                for (int g = prev + 1; g <= cur; g++) d_gstart[g] = i;
            }
        }
    }
    grid_barrier(6);

    // ---- P6: edge scatter: 8-byte float2 RED per edge ----
    for (int e = gtid; e < E; e += gsz) {
        int s = ei[e], d = ei[E + e];
        float4 ni = d_ninfo[s];
        atomicAdd(&d_pq[(size_t)__float_as_int(ni.z) * N + d],
                  make_float2(ni.x, ni.y));
    }
    grid_barrier(7);

    // ---- P7: h2 + fused mean pool ----
    {
        int Beff = d_Beff;
        for (int k = tid; k < Beff * DH; k += 256) { su[k] = d_u[k]; sw[k] = d_w[k]; }
        if (tid < DH) sb2[tid] = b2[tid];
        __syncthreads();

        int ntiles = (N + 63) >> 6;
        int part = tid & 3;
        for (int tt = blockIdx.x; tt < ntiles; tt += gridDim.x) {
            __syncthreads();                        // protect swarp/sg0 reuse
            int i0 = tt * 64;
            if (tid == 0) sg0 = batch[i0];
            __syncthreads();
            int node = i0 + (tid >> 2);
            int g0 = sg0;

            float acc[16];
            #pragma unroll
            for (int k = 0; k < 16; k++) acc[k] = 0.f;
            float dv = 0.f;
            int g = g0;
            if (node < N) {
                float4 ni = d_ninfo[node];
                dv = ni.y;
                g = batch[node];
                {   // self-loop term
                    int bi = __float_as_int(ni.z);
                    const float4* u4 = (const float4*)&su[bi * DH + part * 16];
                    const float4* w4 = (const float4*)&sw[bi * DH + part * 16];
                    #pragma unroll
                    for (int jj = 0; jj < 4; jj++) {
                        float4 u = u4[jj], w = w4[jj];
                        acc[jj * 4 + 0] = fmaf(ni.x, u.x, dv * w.x);
                        acc[jj * 4 + 1] = fmaf(ni.x, u.y, dv * w.y);
                        acc[jj * 4 + 2] = fmaf(ni.x, u.z, dv * w.z);
                        acc[jj * 4 + 3] = fmaf(ni.x, u.w, dv * w.w);
                    }
                }
                for (int b = 0; b < Beff; b++) {
                    float2 pq = d_pq[(size_t)b * N + node];
                    if (pq.y != 0.f) {
                        const float4* u4 = (const float4*)&su[b * DH + part * 16];
                        const float4* w4 = (const float4*)&sw[b * DH + part * 16];
                        #pragma unroll
                        for (int jj = 0; jj < 4; jj++) {
                            float4 u = u4[jj], w = w4[jj];
                            acc[jj*4+0] = fmaf(pq.x, u.x, fmaf(pq.y, w.x, acc[jj*4+0]));
                            acc[jj*4+1] = fmaf(pq.x, u.y, fmaf(pq.y, w.y, acc[jj*4+1]));
                            acc[jj*4+2] = fmaf(pq.x, u.z, fmaf(pq.y, w.z, acc[jj*4+2]));
                            acc[jj*4+3] = fmaf(pq.x, u.w, fmaf(pq.y, w.w, acc[jj*4+3]));
                        }
                    }
                }
            }
            float h[16];
            #pragma unroll
            for (int k = 0; k < 16; k++)
                h[k] = (node < N) ? fmaxf(fmaf(dv, acc[k], sb2[part * 16 + k]), 0.f) : 0.f;

            if (node < N && g != g0) {              // graph-boundary stray
                #pragma unroll
                for (int k = 0; k < 16; k++)
                    atomicAdd(&d_pooled[g * DH + part * 16 + k], h[k]);
                #pragma unroll
                for (int k = 0; k < 16; k++) h[k] = 0.f;
            }
            #pragma unroll
            for (int k = 0; k < 16; k++) {
                h[k] += __shfl_xor_sync(0xffffffffu, h[k], 16);
                h[k] += __shfl_xor_sync(0xffffffffu, h[k], 8);
                h[k] += __shfl_xor_sync(0xffffffffu, h[k], 4);
            }
            int lane = tid & 31, warp = tid >> 5;
            if (lane < 4) {
                #pragma unroll
                for (int k = 0; k < 16; k++) swarp[warp][lane * 16 + k] = h[k];
            }
            __syncthreads();
            if (tid < DH) {
                float tot = 0.f;
                #pragma unroll
                for (int wq = 0; wq < 8; wq++) tot += swarp[wq][tid];
                atomicAdd(&d_pooled[g0 * DH + tid], tot);
            }
        }
    }
    grid_barrier(8);

    // ---- P8: block 0: mean + FC (su reused for fcW) ----
    if (blockIdx.x == 0) {
        for (int k = tid; k < DH * DOUT; k += 256) su[k] = fcW[k];
        __syncthreads();
        for (int idx = tid; idx < G * DOUT; idx += 256) {
            int gg = idx >> 5, o = idx & 31;
            float cntf = (float)(d_gstart[gg + 1] - d_gstart[gg]);
            float inv = 1.f / fmaxf(cntf, 1.f);
            float r = fcb[o];
            #pragma unroll
            for (int f = 0; f < DH; f++)
                r = fmaf(d_pooled[gg * DH + f] * inv, su[f * DOUT + o], r);
            out[idx] = r;
        }
    }

    // ---- exit: last block resets barrier counters for next launch ----
    __syncthreads();
    if (tid == 0) {
        __threadfence();
        unsigned d = atomicAdd(&d_bardone, 1u);
        if (d == gridDim.x - 1) {
            d_barcnt = 0;
            d_bardone = 0;
            __threadfence();
        }
    }
}

extern "C" void kernel_launch(void* const* d_in, const int* in_sizes, int n_in,
                              void* d_out, int out_size) {
    // metadata order: x, edge_index, batch, emb, W1, b1, W2, b2, fcW, fcb
    const int*   ei    = (const int*)d_in[1];
    const int*   batch = (const int*)d_in[2];
    const float* emb   = (const float*)d_in[3];
    const float* W1    = (const float*)d_in[4];
    const float* b1    = (const float*)d_in[5];
    const float* W2    = (const float*)d_in[6];
    const float* b2    = (const float*)d_in[7];
    const float* fcW   = (const float*)d_in[8];
    const float* fcb   = (const float*)d_in[9];
    float* out = (float*)d_out;

    int N = in_sizes[0];
    int E = in_sizes[1] / 2;
    int G = out_size / DOUT;

    int dev = 0;
    cudaGetDevice(&dev);
    int sm = 0;
    cudaDeviceGetAttribute(&sm, cudaDevAttrMultiProcessorCount, dev);
    if (sm <= 0) sm = 148;
    int maxb = 1;
    cudaOccupancyMaxActiveBlocksPerMultiprocessor(&maxb, k_all, 256, 0);
    if (maxb < 1) maxb = 1;
    if (maxb > 4) maxb = 4;
    int grid = sm * maxb;                  // co-resident by construction
    if (grid <= BMAX) grid = BMAX + 1;     // P5 split requires > BMAX blocks

    k_all<<<grid, 256>>>(ei, batch, emb, W1, b1, W2, b2, fcW, fcb, out, N, E, G);
}